// round 2
// baseline (speedup 1.0000x reference)
#include <cuda_runtime.h>
#include <math_constants.h>

#define BATCH 8192
#define DIM   128
#define BM    128
#define BN    128
#define PITCH 129
#define MARGIN_F 0.5f

#define MTILES (BATCH / BM)              // 64
#define NTILES (BATCH / BN)              // 64
#define NPAIRS (MTILES * NTILES)         // 4096
#define GRID_G 296                       // 2 * 148 SMs -> two perfectly full waves

// ---- scratch (no allocations allowed) ----
__device__ float g_norms[BATCH];
__device__ int   g_maxpos[BATCH];   // float bits; dist >= 0 so int order == float order
__device__ int   g_minneg[BATCH];
__device__ float g_psum[BATCH / 256];
__device__ float g_pcnt[BATCH / 256];

// ---- kernel 1: row norms + init accumulators ----
__global__ void prep_kernel(const float* __restrict__ emb) {
    int row  = blockIdx.x * 8 + (threadIdx.x >> 5);
    int lane = threadIdx.x & 31;
    float4 v = reinterpret_cast<const float4*>(emb)[row * 32 + lane];
    float s = v.x * v.x + v.y * v.y + v.z * v.z + v.w * v.w;
    #pragma unroll
    for (int o = 16; o; o >>= 1) s += __shfl_xor_sync(0xffffffffu, s, o);
    if (lane == 0) {
        g_norms[row]  = s;
        g_maxpos[row] = 0xFF800000;  // -inf bits
        g_minneg[row] = 0x7F800000;  // +inf bits
    }
}

// ---- kernel 2: persistent fused GEMM + hardest-pos/neg reduction ----
__global__ __launch_bounds__(256, 1)
void dist_kernel(const float* __restrict__ emb, const int* __restrict__ labels) {
    extern __shared__ float smem[];
    float* As   = smem;                       // [DIM][PITCH], k-major: As[k*PITCH + m]
    float* Bs   = smem + DIM * PITCH;         // [DIM][PITCH]
    float* nrmB = Bs + DIM * PITCH;           // [BN]
    int*   lblB = (int*)(nrmB + BN);          // [BN]

    const int tid = threadIdx.x;
    const int tx  = tid & 15;
    const int ty  = tid >> 4;

    // contiguous chunk of (m,n) tile-pairs, m-major
    int p  = (int)(((long long)blockIdx.x * NPAIRS) / GRID_G);
    int p1 = (int)(((long long)(blockIdx.x + 1) * NPAIRS) / GRID_G);

    while (p < p1) {
        const int mt   = p >> 6;
        const int pend = min(p1, (mt + 1) << 6);
        const int m0   = mt * BM;

        __syncthreads();   // protect As from previous m-range's compute
        for (int idx = tid; idx < BM * DIM; idx += 256) {
            int m = idx >> 7, d = idx & 127;
            As[d * PITCH + m] = emb[(m0 + m) * DIM + d];
        }

        float nrmA[8]; int lblA[8];
        #pragma unroll
        for (int r = 0; r < 8; r++) {
            int m = m0 + ty + 16 * r;
            nrmA[r] = g_norms[m];
            lblA[r] = labels[m];
        }

        float maxpos[8], minneg[8];
        #pragma unroll
        for (int r = 0; r < 8; r++) { maxpos[r] = -CUDART_INF_F; minneg[r] = CUDART_INF_F; }

        for (; p < pend; p++) {
            const int n0 = (p & 63) * BN;
            __syncthreads();   // protect Bs from previous tile's compute; publishes As too
            for (int idx = tid; idx < BN * DIM; idx += 256) {
                int n = idx >> 7, d = idx & 127;
                Bs[d * PITCH + n] = emb[(n0 + n) * DIM + d];
            }
            if (tid < BN) {
                nrmB[tid] = g_norms[n0 + tid];
                lblB[tid] = labels[n0 + tid];
            }
            __syncthreads();

            float acc[8][8];
            #pragma unroll
            for (int r = 0; r < 8; r++)
                #pragma unroll
                for (int c = 0; c < 8; c++) acc[r][c] = 0.f;

            #pragma unroll 4
            for (int k = 0; k < DIM; k++) {
                float a[8], b[8];
                #pragma unroll
                for (int r = 0; r < 8; r++) a[r] = As[k * PITCH + ty + 16 * r];
                #pragma unroll
                for (int c = 0; c < 8; c++) b[c] = Bs[k * PITCH + tx + 16 * c];
                #pragma unroll
                for (int r = 0; r < 8; r++)
                    #pragma unroll
                    for (int c = 0; c < 8; c++) acc[r][c] = fmaf(a[r], b[c], acc[r][c]);
            }

            #pragma unroll
            for (int r = 0; r < 8; r++) {
                int m = m0 + ty + 16 * r;
                #pragma unroll
                for (int c = 0; c < 8; c++) {
                    int nn = tx + 16 * c;
                    int n  = n0 + nn;
                    float d2   = fmaf(-2.f, acc[r][c], nrmA[r] + nrmB[nn]);
                    float dist = sqrtf(fmaxf(d2, 0.f));
                    if (m != n) {
                        if (lblA[r] == lblB[nn]) maxpos[r] = fmaxf(maxpos[r], dist);
                        else                     minneg[r] = fminf(minneg[r], dist);
                    }
                }
            }
        }

        // Reduce over the 16 tx lanes, then one atomic per row for this m-range
        #pragma unroll
        for (int r = 0; r < 8; r++) {
            #pragma unroll
            for (int o = 8; o; o >>= 1) {
                maxpos[r] = fmaxf(maxpos[r], __shfl_xor_sync(0xffffffffu, maxpos[r], o));
                minneg[r] = fminf(minneg[r], __shfl_xor_sync(0xffffffffu, minneg[r], o));
            }
            if (tx == 0) {
                int m = m0 + ty + 16 * r;
                atomicMax(&g_maxpos[m], __float_as_int(maxpos[r]));  // -inf bits = no-op
                atomicMin(&g_minneg[m], __float_as_int(minneg[r]));  // +inf bits = no-op
            }
        }
    }
}

// ---- kernel 3: per-anchor loss + deterministic partial sums ----
__global__ void reduce_kernel() {
    __shared__ float ssum[256], scnt[256];
    int i = blockIdx.x * 256 + threadIdx.x;
    int mp = g_maxpos[i];
    int mn = g_minneg[i];
    bool valid = (mp != (int)0xFF800000) && (mn != 0x7F800000);
    float per = fmaxf(__int_as_float(mp) - __int_as_float(mn) + MARGIN_F, 0.f);
    ssum[threadIdx.x] = valid ? per : 0.f;
    scnt[threadIdx.x] = valid ? 1.f : 0.f;
    __syncthreads();
    for (int s = 128; s; s >>= 1) {
        if (threadIdx.x < s) {
            ssum[threadIdx.x] += ssum[threadIdx.x + s];
            scnt[threadIdx.x] += scnt[threadIdx.x + s];
        }
        __syncthreads();
    }
    if (threadIdx.x == 0) { g_psum[blockIdx.x] = ssum[0]; g_pcnt[blockIdx.x] = scnt[0]; }
}

__global__ void final_kernel(float* __restrict__ out) {
    float s = 0.f, c = 0.f;
    for (int i = 0; i < BATCH / 256; i++) { s += g_psum[i]; c += g_pcnt[i]; }
    out[0] = s / fmaxf(c, 1.f);
}

extern "C" void kernel_launch(void* const* d_in, const int* in_sizes, int n_in,
                              void* d_out, int out_size) {
    const float* emb = (const float*)d_in[0];
    const int*   lbl = (const int*)d_in[1];   // jax int64 downcasts to int32 (no x64)
    (void)in_sizes; (void)n_in; (void)out_size;

    const size_t smem = (size_t)(2 * DIM * PITCH + BN) * sizeof(float) + BN * sizeof(int);
    cudaFuncSetAttribute(dist_kernel, cudaFuncAttributeMaxDynamicSharedMemorySize, (int)smem);

    prep_kernel<<<BATCH / 8, 256>>>(emb);
    dist_kernel<<<GRID_G, 256, smem>>>(emb, lbl);
    reduce_kernel<<<BATCH / 256, 256>>>();
    final_kernel<<<1, 1>>>((float*)d_out);
}

// round 4
// speedup vs baseline: 1.8976x; 1.8976x over previous
#include <cuda_runtime.h>
#include <cuda_bf16.h>
#include <math_constants.h>
#include <cstdint>

#define BATCH 8192
#define DIM   128
#define BM    128
#define BN    128
#define MARGIN_F 0.5f

#define MTILES (BATCH / BM)              // 64
#define NTILES (BATCH / BN)              // 64
#define NPAIRS (MTILES * NTILES)         // 4096
#define GRID_G 148                       // persistent, 1 CTA/SM

#define ROWB 528                         // smem row pitch: 264 bf16 (33*16B, LDSM conflict-free)
#define TILE_B (128 * ROWB)              // 67584
#define SM_A    0
#define SM_B0   (TILE_B)
#define SM_B1   (2 * TILE_B)
#define SM_NRM0 (3 * TILE_B)             // 202752
#define SM_LBL0 (SM_NRM0 + 512)
#define SM_NRM1 (SM_LBL0 + 512)
#define SM_LBL1 (SM_NRM1 + 512)
#define SM_TOTAL (SM_LBL1 + 512)         // 204800

// ---- scratch (no allocations allowed) ----
__device__ float          g_norms[BATCH];
__device__ int            g_maxpos[BATCH];   // d^2 float bits (clamped >=0: int order == float order)
__device__ int            g_minneg[BATCH];
__device__ __nv_bfloat16  g_sp[BATCH * 2 * DIM];  // per row: [0..127]=hi, [128..255]=lo

// ================= helpers =================
__device__ __forceinline__ uint32_t smem_u32(const void* p) {
    uint32_t a;
    asm("{ .reg .u64 t; cvta.to.shared.u64 t, %1; cvt.u32.u64 %0, t; }" : "=r"(a) : "l"(p));
    return a;
}
__device__ __forceinline__ void cp16(uint32_t dst, const void* src) {
    asm volatile("cp.async.cg.shared.global [%0], [%1], 16;" :: "r"(dst), "l"(src));
}
#define CP_COMMIT() asm volatile("cp.async.commit_group;" ::: "memory")
#define CP_WAIT(n)  asm volatile("cp.async.wait_group %0;" :: "n"(n) : "memory")

#define LDSM4(r, addr) \
    asm volatile("ldmatrix.sync.aligned.m8n8.x4.shared.b16 {%0,%1,%2,%3}, [%4];" \
                 : "=r"((r)[0]), "=r"((r)[1]), "=r"((r)[2]), "=r"((r)[3]) : "r"(addr))

#define MMA16816(d, a, b) \
    asm volatile("mma.sync.aligned.m16n8k16.row.col.f32.bf16.bf16.f32 " \
                 "{%0,%1,%2,%3}, {%4,%5,%6,%7}, {%8,%9}, {%0,%1,%2,%3};" \
                 : "+f"((d)[0]), "+f"((d)[1]), "+f"((d)[2]), "+f"((d)[3]) \
                 : "r"((a)[0]), "r"((a)[1]), "r"((a)[2]), "r"((a)[3]), \
                   "r"((b)[0]), "r"((b)[1]))

// ---- kernel 1: norms + bf16 hi/lo split + init accumulators ----
__global__ void prep_kernel(const float* __restrict__ emb) {
    int row  = blockIdx.x * 8 + (threadIdx.x >> 5);
    int lane = threadIdx.x & 31;
    float4 v = reinterpret_cast<const float4*>(emb)[row * 32 + lane];
    float s = v.x * v.x + v.y * v.y + v.z * v.z + v.w * v.w;
    #pragma unroll
    for (int o = 16; o; o >>= 1) s += __shfl_xor_sync(0xffffffffu, s, o);
    if (lane == 0) {
        g_norms[row]  = s;
        g_maxpos[row] = 0xFF800000;  // -inf bits
        g_minneg[row] = 0x7F800000;  // +inf bits
    }
    __nv_bfloat16 h0 = __float2bfloat16_rn(v.x), h1 = __float2bfloat16_rn(v.y);
    __nv_bfloat16 h2 = __float2bfloat16_rn(v.z), h3 = __float2bfloat16_rn(v.w);
    __nv_bfloat16 l0 = __float2bfloat16_rn(v.x - __bfloat162float(h0));
    __nv_bfloat16 l1 = __float2bfloat16_rn(v.y - __bfloat162float(h1));
    __nv_bfloat16 l2 = __float2bfloat16_rn(v.z - __bfloat162float(h2));
    __nv_bfloat16 l3 = __float2bfloat16_rn(v.w - __bfloat162float(h3));
    __nv_bfloat162* dst = reinterpret_cast<__nv_bfloat162*>(g_sp + row * 256);
    dst[lane * 2 + 0]      = __nv_bfloat162(h0, h1);
    dst[lane * 2 + 1]      = __nv_bfloat162(h2, h3);
    dst[64 + lane * 2 + 0] = __nv_bfloat162(l0, l1);
    dst[64 + lane * 2 + 1] = __nv_bfloat162(l2, l3);
}

// async-copy one [128 x 256 bf16] tile into pitched smem
__device__ __forceinline__ void load_tile_async(const char* __restrict__ src,
                                                uint32_t sdst, int tid) {
    #pragma unroll
    for (int i = tid; i < 4096; i += 256) {
        int row = i >> 5, ch = i & 31;
        cp16(sdst + row * ROWB + ch * 16, src + row * 512 + ch * 16);
    }
}

// ---- kernel 2: persistent mma.sync GEMM + fused hardest-pos/neg (d^2 space) ----
__global__ __launch_bounds__(256, 1)
void dist_kernel(const int* __restrict__ labels) {
    extern __shared__ char smem[];
    const uint32_t sbase = smem_u32(smem);
    const int tid   = threadIdx.x;
    const int warp  = tid >> 5;
    const int lane  = tid & 31;
    const int mwarp = warp & 3;          // 4 warps over M (32 rows each)
    const int nwarp = warp >> 2;         // 2 warps over N (64 cols each)

    float* nrmS[2] = { (float*)(smem + SM_NRM0), (float*)(smem + SM_NRM1) };
    int*   lblS[2] = { (int*)  (smem + SM_LBL0), (int*)  (smem + SM_LBL1) };
    const uint32_t sBO[2] = { sbase + SM_B0, sbase + SM_B1 };

    // per-thread ldmatrix base offsets
    const uint32_t aBase = sbase + SM_A +
        (uint32_t)(mwarp * 32 + (lane & 15)) * ROWB + ((lane >> 4) * 16);
    const uint32_t bRow  =
        (uint32_t)(nwarp * 64 + (lane & 7) + ((lane >> 4) & 1) * 8) * ROWB +
        (((lane >> 3) & 1) * 16);

    int p  = (int)(((long long)blockIdx.x       * NPAIRS) / GRID_G);
    int p1 = (int)(((long long)(blockIdx.x + 1) * NPAIRS) / GRID_G);

    while (p < p1) {
        const int mt0  = p >> 6;
        const int pend = min(p1, (mt0 + 1) << 6);
        const int m0   = mt0 * BM;

        __syncthreads();  // previous range fully done with all smem buffers

        // rows this thread owns in the epilogue: mwarp*32 + i*8 + lane/4, i=0..3
        float nrmA[4]; int lblA[4], mrowA[4];
        #pragma unroll
        for (int i = 0; i < 4; i++) {
            int rl = mwarp * 32 + ((i >> 1) * 16) + ((i & 1) * 8) + (lane >> 2);
            mrowA[i] = m0 + rl;
            nrmA[i]  = g_norms[mrowA[i]];
            lblA[i]  = labels[mrowA[i]];
        }
        float maxpos[4], minneg[4];
        #pragma unroll
        for (int i = 0; i < 4; i++) { maxpos[i] = -CUDART_INF_F; minneg[i] = CUDART_INF_F; }

        // prologue: A + B(p) in one cp.async group
        load_tile_async((const char*)(g_sp + (size_t)m0 * 256), sbase + SM_A, tid);
        {
            const int n0 = (p & 63) * BN;
            load_tile_async((const char*)(g_sp + (size_t)n0 * 256), sBO[0], tid);
            if (tid < BN) { nrmS[0][tid] = g_norms[n0 + tid]; lblS[0][tid] = labels[n0 + tid]; }
        }
        CP_COMMIT();

        int cur = 0;
        for (int j = p; j < pend; j++) {
            const int n0 = (j & 63) * BN;
            const bool have_next = (j + 1 < pend);
            if (have_next) {
                const int n0n = ((j + 1) & 63) * BN;
                load_tile_async((const char*)(g_sp + (size_t)n0n * 256), sBO[cur ^ 1], tid);
                if (tid < BN) {
                    nrmS[cur ^ 1][tid] = g_norms[n0n + tid];
                    lblS[cur ^ 1][tid] = labels[n0n + tid];
                }
                CP_COMMIT();
                CP_WAIT(1);
            } else {
                CP_WAIT(0);
            }
            __syncthreads();      // B(j) (and A) visible

            // ---- 3-pass bf16-split GEMM on tile pair (m0, n0) ----
            float acc[2][8][4];
            #pragma unroll
            for (int mt = 0; mt < 2; mt++)
                #pragma unroll
                for (int nt = 0; nt < 8; nt++)
                    #pragma unroll
                    for (int c = 0; c < 4; c++) acc[mt][nt][c] = 0.f;

            const uint32_t bBase = sBO[cur] + bRow;
            #pragma unroll
            for (int pass = 0; pass < 3; pass++) {
                const uint32_t ao = (pass == 2) ? 256u : 0u;  // A lo half (bytes)
                const uint32_t bo = (pass == 1) ? 256u : 0u;  // B lo half
                #pragma unroll
                for (int ks = 0; ks < 8; ks++) {
                    uint32_t a0[4], a1[4], b[4][4];
                    LDSM4(a0, aBase + ao + ks * 32);
                    LDSM4(a1, aBase + ao + ks * 32 + 16 * ROWB);
                    #pragma unroll
                    for (int np = 0; np < 4; np++)
                        LDSM4(b[np], bBase + (uint32_t)(np * 16) * ROWB + bo + ks * 32);
                    #pragma unroll
                    for (int nt = 0; nt < 8; nt++) {
                        uint32_t* bp = &b[nt >> 1][(nt & 1) * 2];
                        MMA16816(acc[0][nt], a0, bp);
                        MMA16816(acc[1][nt], a1, bp);
                    }
                }
            }

            // ---- fused epilogue in d^2 space ----
            {
                const float* nB = nrmS[cur];
                const int*   lB = lblS[cur];
                #pragma unroll
                for (int mt = 0; mt < 2; mt++)
                    #pragma unroll
                    for (int half = 0; half < 2; half++) {
                        const int i   = mt * 2 + half;
                        const float nA = nrmA[i];
                        const int   lA = lblA[i];
                        const int   mr = mrowA[i];
                        #pragma unroll
                        for (int nt = 0; nt < 8; nt++) {
                            #pragma unroll
                            for (int cc = 0; cc < 2; cc++) {
                                int col = nwarp * 64 + nt * 8 + (lane & 3) * 2 + cc;
                                float dot = acc[mt][nt][half * 2 + cc];
                                float d2  = fmaxf(fmaf(-2.f, dot, nA + nB[col]), 0.f);
                                if (mr != n0 + col) {
                                    if (lA == lB[col]) maxpos[i] = fmaxf(maxpos[i], d2);
                                    else               minneg[i] = fminf(minneg[i], d2);
                                }
                            }
                        }
                    }
            }
            __syncthreads();      // all reads of buf[cur] done before it is refilled
            if (have_next) cur ^= 1;
        }

        // reduce across the 4 lanes of each quad (same rows), then atomics
        #pragma unroll
        for (int i = 0; i < 4; i++) {
            #pragma unroll
            for (int o = 1; o <= 2; o <<= 1) {
                maxpos[i] = fmaxf(maxpos[i], __shfl_xor_sync(0xffffffffu, maxpos[i], o));
                minneg[i] = fminf(minneg[i], __shfl_xor_sync(0xffffffffu, minneg[i], o));
            }
        }
        if ((lane & 3) == 0) {
            #pragma unroll
            for (int i = 0; i < 4; i++) {
                atomicMax(&g_maxpos[mrowA[i]], __float_as_int(maxpos[i]));
                atomicMin(&g_minneg[mrowA[i]], __float_as_int(minneg[i]));
            }
        }
        p = pend;
    }
}

// ---- kernel 3: single-block finalize (sqrt applied here; monotone) ----
__global__ __launch_bounds__(1024)
void finalize_kernel(float* __restrict__ out) {
    __shared__ float ssum[1024], scnt[1024];
    float s = 0.f, c = 0.f;
    for (int i = threadIdx.x; i < BATCH; i += 1024) {
        int mp = g_maxpos[i], mn = g_minneg[i];
        bool valid = (mp != (int)0xFF800000) && (mn != 0x7F800000);
        float hp = sqrtf(fmaxf(__int_as_float(mp), 0.f));
        float hn = sqrtf(fmaxf(__int_as_float(mn), 0.f));
        float per = fmaxf(hp - hn + MARGIN_F, 0.f);
        if (valid) { s += per; c += 1.f; }
    }
    ssum[threadIdx.x] = s; scnt[threadIdx.x] = c;
    __syncthreads();
    for (int st = 512; st; st >>= 1) {
        if (threadIdx.x < st) {
            ssum[threadIdx.x] += ssum[threadIdx.x + st];
            scnt[threadIdx.x] += scnt[threadIdx.x + st];
        }
        __syncthreads();
    }
    if (threadIdx.x == 0) out[0] = ssum[0] / fmaxf(scnt[0], 1.f);
}

extern "C" void kernel_launch(void* const* d_in, const int* in_sizes, int n_in,
                              void* d_out, int out_size) {
    const float* emb = (const float*)d_in[0];
    const int*   lbl = (const int*)d_in[1];   // jax int64 -> int32 (no x64)
    (void)in_sizes; (void)n_in; (void)out_size;

    cudaFuncSetAttribute(dist_kernel, cudaFuncAttributeMaxDynamicSharedMemorySize, SM_TOTAL);

    prep_kernel<<<BATCH / 8, 256>>>(emb);
    dist_kernel<<<GRID_G, 256, SM_TOTAL>>>(lbl);
    finalize_kernel<<<1, 1024>>>((float*)d_out);
}

// round 5
// speedup vs baseline: 4.2940x; 2.2629x over previous
#include <cuda_runtime.h>
#include <cuda_bf16.h>
#include <math_constants.h>
#include <cstdint>

#define BATCH 8192
#define DIM   128
#define BM    128
#define BN    128
#define MARGIN_F 0.5f

#define MTILES 64
#define NPAIRS_SYM 2080                  // 64*65/2 upper-triangular tile pairs
#define GRID_G 148                       // persistent, 1 CTA/SM

#define ROWB 528                         // smem row pitch: 264 bf16 (33*16B, LDSM conflict-free)
#define TILE_B (128 * ROWB)              // 67584
#define SM_A    0
#define SM_B0   (TILE_B)
#define SM_B1   (2 * TILE_B)
#define SM_NRM0 (3 * TILE_B)             // 202752
#define SM_LBL0 (SM_NRM0 + 512)
#define SM_NRM1 (SM_LBL0 + 512)
#define SM_LBL1 (SM_NRM1 + 512)
#define SM_CMAX (SM_LBL1 + 512)          // [4][128] float per-mwarp col max
#define SM_CMIN (SM_CMAX + 2048)         // [4][128] float per-mwarp col min
#define SM_TOTAL (SM_CMIN + 2048)        // 208896

// ---- scratch (no allocations allowed) ----
__device__ float          g_norms[BATCH];
__device__ int            g_maxpos[BATCH];   // d^2 float bits (clamped >=0: int order == float order)
__device__ int            g_minneg[BATCH];
__device__ __nv_bfloat16  g_sp[BATCH * 2 * DIM];  // per row: [0..127]=hi, [128..255]=lo

// ================= helpers =================
__device__ __forceinline__ uint32_t smem_u32(const void* p) {
    uint32_t a;
    asm("{ .reg .u64 t; cvta.to.shared.u64 t, %1; cvt.u32.u64 %0, t; }" : "=r"(a) : "l"(p));
    return a;
}
__device__ __forceinline__ void cp16(uint32_t dst, const void* src) {
    asm volatile("cp.async.cg.shared.global [%0], [%1], 16;" :: "r"(dst), "l"(src));
}
#define CP_COMMIT() asm volatile("cp.async.commit_group;" ::: "memory")
#define CP_WAIT(n)  asm volatile("cp.async.wait_group %0;" :: "n"(n) : "memory")

#define LDSM4(r, addr) \
    asm volatile("ldmatrix.sync.aligned.m8n8.x4.shared.b16 {%0,%1,%2,%3}, [%4];" \
                 : "=r"((r)[0]), "=r"((r)[1]), "=r"((r)[2]), "=r"((r)[3]) : "r"(addr))

#define MMA16816(d, a, b) \
    asm volatile("mma.sync.aligned.m16n8k16.row.col.f32.bf16.bf16.f32 " \
                 "{%0,%1,%2,%3}, {%4,%5,%6,%7}, {%8,%9}, {%0,%1,%2,%3};" \
                 : "+f"((d)[0]), "+f"((d)[1]), "+f"((d)[2]), "+f"((d)[3]) \
                 : "r"((a)[0]), "r"((a)[1]), "r"((a)[2]), "r"((a)[3]), \
                   "r"((b)[0]), "r"((b)[1]))

// ---- kernel 1: norms + bf16 hi/lo split + init accumulators ----
__global__ void prep_kernel(const float* __restrict__ emb) {
    int row  = blockIdx.x * 8 + (threadIdx.x >> 5);
    int lane = threadIdx.x & 31;
    float4 v = reinterpret_cast<const float4*>(emb)[row * 32 + lane];
    float s = v.x * v.x + v.y * v.y + v.z * v.z + v.w * v.w;
    #pragma unroll
    for (int o = 16; o; o >>= 1) s += __shfl_xor_sync(0xffffffffu, s, o);
    if (lane == 0) {
        g_norms[row]  = s;
        g_maxpos[row] = 0xFF800000;  // -inf bits
        g_minneg[row] = 0x7F800000;  // +inf bits
    }
    __nv_bfloat16 h0 = __float2bfloat16_rn(v.x), h1 = __float2bfloat16_rn(v.y);
    __nv_bfloat16 h2 = __float2bfloat16_rn(v.z), h3 = __float2bfloat16_rn(v.w);
    __nv_bfloat16 l0 = __float2bfloat16_rn(v.x - __bfloat162float(h0));
    __nv_bfloat16 l1 = __float2bfloat16_rn(v.y - __bfloat162float(h1));
    __nv_bfloat16 l2 = __float2bfloat16_rn(v.z - __bfloat162float(h2));
    __nv_bfloat16 l3 = __float2bfloat16_rn(v.w - __bfloat162float(h3));
    __nv_bfloat162* dst = reinterpret_cast<__nv_bfloat162*>(g_sp + row * 256);
    dst[lane * 2 + 0]      = __nv_bfloat162(h0, h1);
    dst[lane * 2 + 1]      = __nv_bfloat162(h2, h3);
    dst[64 + lane * 2 + 0] = __nv_bfloat162(l0, l1);
    dst[64 + lane * 2 + 1] = __nv_bfloat162(l2, l3);
}

// async-copy one [128 x 256 bf16] tile into pitched smem
__device__ __forceinline__ void load_tile_async(const char* __restrict__ src,
                                                uint32_t sdst, int tid) {
    #pragma unroll
    for (int i = tid; i < 4096; i += 256) {
        int row = i >> 5, ch = i & 31;
        cp16(sdst + row * ROWB + ch * 16, src + row * 512 + ch * 16);
    }
}

// ---- kernel 2: persistent symmetric mma.sync GEMM + fused hardest-pos/neg (d^2 space) ----
__global__ __launch_bounds__(256, 1)
void dist_kernel(const int* __restrict__ labels) {
    extern __shared__ char smem[];
    const uint32_t sbase = smem_u32(smem);
    const int tid   = threadIdx.x;
    const int warp  = tid >> 5;
    const int lane  = tid & 31;
    const int mwarp = warp & 3;          // 4 warps over M (32 rows each)
    const int nwarp = warp >> 2;         // 2 warps over N (64 cols each)

    float* nrmS[2] = { (float*)(smem + SM_NRM0), (float*)(smem + SM_NRM1) };
    int*   lblS[2] = { (int*)  (smem + SM_LBL0), (int*)  (smem + SM_LBL1) };
    float* credMax = (float*)(smem + SM_CMAX);   // [4][128]
    float* credMin = (float*)(smem + SM_CMIN);   // [4][128]
    const uint32_t sBO[2] = { sbase + SM_B0, sbase + SM_B1 };

    // per-thread ldmatrix base offsets
    const uint32_t aBase = sbase + SM_A +
        (uint32_t)(mwarp * 32 + (lane & 15)) * ROWB + ((lane >> 4) * 16);
    const uint32_t bRow  =
        (uint32_t)(nwarp * 64 + (lane & 7) + ((lane >> 4) & 1) * 8) * ROWB +
        (((lane >> 3) & 1) * 16);

    int p  = (int)(((long long)blockIdx.x       * NPAIRS_SYM) / GRID_G);
    int p1 = (int)(((long long)(blockIdx.x + 1) * NPAIRS_SYM) / GRID_G);

    int mt = 0, S = 0;                   // row decode: row mt starts at linear index S
    while (S + (MTILES - mt) <= p) { S += MTILES - mt; mt++; }

    while (p < p1) {
        const int rowEnd = S + (MTILES - mt);
        const int pend   = min(p1, rowEnd);
        const int m0     = mt * BM;

        __syncthreads();  // previous range fully done with all smem buffers

        float nrmA[4]; int lblA[4], mrowA[4];
        #pragma unroll
        for (int i = 0; i < 4; i++) {
            int rl = mwarp * 32 + ((i >> 1) * 16) + ((i & 1) * 8) + (lane >> 2);
            mrowA[i] = m0 + rl;
            nrmA[i]  = g_norms[mrowA[i]];
            lblA[i]  = labels[mrowA[i]];
        }
        float maxpos[4], minneg[4];
        #pragma unroll
        for (int i = 0; i < 4; i++) { maxpos[i] = -CUDART_INF_F; minneg[i] = CUDART_INF_F; }

        // prologue: A + B(first) in one cp.async group
        load_tile_async((const char*)(g_sp + (size_t)m0 * 256), sbase + SM_A, tid);
        {
            const int n0 = (mt + (p - S)) * BN;
            load_tile_async((const char*)(g_sp + (size_t)n0 * 256), sBO[0], tid);
            if (tid < BN) { nrmS[0][tid] = g_norms[n0 + tid]; lblS[0][tid] = labels[n0 + tid]; }
        }
        CP_COMMIT();

        int cur = 0;
        for (int j = p; j < pend; j++) {
            const int ntile = mt + (j - S);
            const int n0    = ntile * BN;
            const bool offd = (ntile != mt);
            const bool have_next = (j + 1 < pend);
            if (have_next) {
                const int n0n = (ntile + 1) * BN;
                load_tile_async((const char*)(g_sp + (size_t)n0n * 256), sBO[cur ^ 1], tid);
                if (tid < BN) {
                    nrmS[cur ^ 1][tid] = g_norms[n0n + tid];
                    lblS[cur ^ 1][tid] = labels[n0n + tid];
                }
                CP_COMMIT();
                CP_WAIT(1);
            } else {
                CP_WAIT(0);
            }
            __syncthreads();      // B(j) (and A) visible

            // ---- 3-pass bf16-split GEMM on tile pair (mt, ntile) ----
            float acc[2][8][4];
            #pragma unroll
            for (int a = 0; a < 2; a++)
                #pragma unroll
                for (int b = 0; b < 8; b++)
                    #pragma unroll
                    for (int c = 0; c < 4; c++) acc[a][b][c] = 0.f;

            const uint32_t bBase = sBO[cur] + bRow;
            #pragma unroll
            for (int pass = 0; pass < 3; pass++) {
                const uint32_t ao = (pass == 2) ? 256u : 0u;  // A lo half (bytes)
                const uint32_t bo = (pass == 1) ? 256u : 0u;  // B lo half
                #pragma unroll
                for (int ks = 0; ks < 8; ks++) {
                    uint32_t a0[4], a1[4], b[4][4];
                    LDSM4(a0, aBase + ao + ks * 32);
                    LDSM4(a1, aBase + ao + ks * 32 + 16 * ROWB);
                    #pragma unroll
                    for (int np = 0; np < 4; np++)
                        LDSM4(b[np], bBase + (uint32_t)(np * 16) * ROWB + bo + ks * 32);
                    #pragma unroll
                    for (int nt = 0; nt < 8; nt++) {
                        uint32_t* bp = &b[nt >> 1][(nt & 1) * 2];
                        MMA16816(acc[0][nt], a0, bp);
                        MMA16816(acc[1][nt], a1, bp);
                    }
                }
            }

            // ---- fused epilogue in d^2 space: row-side always, col-side if off-diagonal ----
            float cmax[16], cmin[16];
            #pragma unroll
            for (int k = 0; k < 16; k++) { cmax[k] = -CUDART_INF_F; cmin[k] = CUDART_INF_F; }
            {
                const float* nB = nrmS[cur];
                const int*   lB = lblS[cur];
                #pragma unroll
                for (int mtl = 0; mtl < 2; mtl++)
                    #pragma unroll
                    for (int half = 0; half < 2; half++) {
                        const int i   = mtl * 2 + half;
                        const float nA = nrmA[i];
                        const int   lA = lblA[i];
                        const int   mr = mrowA[i];
                        #pragma unroll
                        for (int nt = 0; nt < 8; nt++) {
                            #pragma unroll
                            for (int cc = 0; cc < 2; cc++) {
                                int col = nwarp * 64 + nt * 8 + (lane & 3) * 2 + cc;
                                float dot = acc[mtl][nt][half * 2 + cc];
                                float d2  = fmaxf(fmaf(-2.f, dot, nA + nB[col]), 0.f);
                                bool same = (lA == lB[col]);
                                if (mr != n0 + col) {
                                    if (same) maxpos[i] = fmaxf(maxpos[i], d2);
                                    else      minneg[i] = fminf(minneg[i], d2);
                                }
                                if (offd) {
                                    int k = nt * 2 + cc;
                                    if (same) cmax[k] = fmaxf(cmax[k], d2);
                                    else      cmin[k] = fminf(cmin[k], d2);
                                }
                            }
                        }
                    }
            }
            if (offd) {
                // reduce columns over the 8 row-groups (lanes differing in bits 2..4)
                #pragma unroll
                for (int k = 0; k < 16; k++) {
                    #pragma unroll
                    for (int o = 4; o <= 16; o <<= 1) {
                        cmax[k] = fmaxf(cmax[k], __shfl_xor_sync(0xffffffffu, cmax[k], o));
                        cmin[k] = fminf(cmin[k], __shfl_xor_sync(0xffffffffu, cmin[k], o));
                    }
                }
                if ((lane >> 2) == 0) {
                    #pragma unroll
                    for (int k = 0; k < 16; k++) {
                        int col = nwarp * 64 + (k >> 1) * 8 + (lane & 3) * 2 + (k & 1);
                        credMax[mwarp * 128 + col] = cmax[k];
                        credMin[mwarp * 128 + col] = cmin[k];
                    }
                }
            }
            __syncthreads();      // buf[cur] reads done; colred staged
            if (offd && tid < 128) {
                float mx = fmaxf(fmaxf(credMax[tid],       credMax[128 + tid]),
                                 fmaxf(credMax[256 + tid], credMax[384 + tid]));
                float mn = fminf(fminf(credMin[tid],       credMin[128 + tid]),
                                 fminf(credMin[256 + tid], credMin[384 + tid]));
                atomicMax(&g_maxpos[n0 + tid], __float_as_int(mx));  // -inf bits = no-op
                atomicMin(&g_minneg[n0 + tid], __float_as_int(mn));  // +inf bits = no-op
            }
            if (have_next) cur ^= 1;
        }

        // row-side: reduce across the 4 lanes of each quad, then atomics
        #pragma unroll
        for (int i = 0; i < 4; i++) {
            #pragma unroll
            for (int o = 1; o <= 2; o <<= 1) {
                maxpos[i] = fmaxf(maxpos[i], __shfl_xor_sync(0xffffffffu, maxpos[i], o));
                minneg[i] = fminf(minneg[i], __shfl_xor_sync(0xffffffffu, minneg[i], o));
            }
        }
        if ((lane & 3) == 0) {
            #pragma unroll
            for (int i = 0; i < 4; i++) {
                atomicMax(&g_maxpos[mrowA[i]], __float_as_int(maxpos[i]));
                atomicMin(&g_minneg[mrowA[i]], __float_as_int(minneg[i]));
            }
        }
        p = pend;
        if (p == rowEnd) { S = rowEnd; mt++; }
    }
}

// ---- kernel 3: single-block finalize (sqrt applied here; monotone) ----
__global__ __launch_bounds__(1024)
void finalize_kernel(float* __restrict__ out) {
    __shared__ float ssum[1024], scnt[1024];
    float s = 0.f, c = 0.f;
    for (int i = threadIdx.x; i < BATCH; i += 1024) {
        int mp = g_maxpos[i], mn = g_minneg[i];
        bool valid = (mp != (int)0xFF800000) && (mn != 0x7F800000);
        float hp = sqrtf(fmaxf(__int_as_float(mp), 0.f));
        float hn = sqrtf(fmaxf(__int_as_float(mn), 0.f));
        float per = fmaxf(hp - hn + MARGIN_F, 0.f);
        if (valid) { s += per; c += 1.f; }
    }
    ssum[threadIdx.x] = s; scnt[threadIdx.x] = c;
    __syncthreads();
    for (int st = 512; st; st >>= 1) {
        if (threadIdx.x < st) {
            ssum[threadIdx.x] += ssum[threadIdx.x + st];
            scnt[threadIdx.x] += scnt[threadIdx.x + st];
        }
        __syncthreads();
    }
    if (threadIdx.x == 0) out[0] = ssum[0] / fmaxf(scnt[0], 1.f);
}

extern "C" void kernel_launch(void* const* d_in, const int* in_sizes, int n_in,
                              void* d_out, int out_size) {
    const float* emb = (const float*)d_in[0];
    const int*   lbl = (const int*)d_in[1];   // jax int64 -> int32 (no x64)
    (void)in_sizes; (void)n_in; (void)out_size;

    cudaFuncSetAttribute(dist_kernel, cudaFuncAttributeMaxDynamicSharedMemorySize, SM_TOTAL);

    prep_kernel<<<BATCH / 8, 256>>>(emb);
    dist_kernel<<<GRID_G, 256, SM_TOTAL>>>(lbl);
    finalize_kernel<<<1, 1024>>>((float*)d_out);
}